// round 1
// baseline (speedup 1.0000x reference)
#include <cuda_runtime.h>
#include <math.h>

// Problem constants (fixed shapes)
#define B_ 32
#define C_ 256
#define S_ 1024
#define HID_ 128
#define NPATH_ 4

// ---------------------------------------------------------------------------
// Static device scratch (no allocation allowed at runtime)
// ---------------------------------------------------------------------------
__device__ float g_Ql[B_ * C_ * S_];              // 32 MB  Q from lidar (channel-major [b][c][s])
__device__ float g_Kl[B_ * C_ * S_];              // 32 MB  K from lidar
__device__ float g_Qh[B_ * C_ * S_];              // 32 MB  Q from hsi
__device__ float g_Kh[B_ * C_ * S_];              // 32 MB  K from hsi
__device__ float g_QV1[B_ * C_ * S_];             // 32 MB  Ql * (Wv@hsi+bv)
__device__ float g_QV2[B_ * C_ * S_];             // 32 MB  Qh * (Wv@lidar+bv)
__device__ float g_P[2LL * B_ * S_ * S_];         // 256 MB attention probs, [dir][b][s][t]
__device__ float g_cat[B_ * 2 * C_ * S_];         // 64 MB  [b][2c][s]: ch 0..255 = l_emb, 256..511 = h_emb
__device__ float g_pool[B_ * 2 * C_];             // router pooled features

// ---------------------------------------------------------------------------
// Generic tiled SGEMM: C[m,n] = sum_k opA(m,k) * opB(k,n)  (+ epilogue)
//   AL=0: A stored [m][k] (k contiguous, stride lda)
//   AL=1: A stored [k][m] (m contiguous, stride lda)
//   BL=0: B stored [k][n] (n contiguous, stride ldb)
//   BL=1: B stored [n][k] (k contiguous, stride ldb)
//   EPI=0: none; EPI=1: +bias[m]; EPI=2: (acc+bias[m])*X[m,n]; EPI=3: acc+bias[m]+X[m,n]
// Requires M%64==0, N%64==0, K%16==0 (true for all uses here).
// grid = (N/64, M/64, batch), block = 256
// ---------------------------------------------------------------------------
constexpr int BM = 64, BN = 64, BKT = 16, TM = 4, TN = 4;

template<int AL, int BL, int EPI>
__global__ __launch_bounds__(256) void gemm_k(
    const float* __restrict__ A, const float* __restrict__ B,
    float* __restrict__ C, const float* __restrict__ bias,
    const float* __restrict__ X,
    int K, int lda, int ldb, int ldc, int ldx,
    long long sA, long long sB, long long sC, long long sX)
{
    // +4 pad keeps 16B row alignment (68*4 = 272 = 17*16) and breaks the
    // 64-float column bank pattern for the transposed store paths.
    __shared__ float As[BKT][BM + 4];
    __shared__ float Bs[BKT][BN + 4];

    long long bz = blockIdx.z;
    A += bz * sA;
    B += bz * sB;
    C += bz * sC;
    const float* Xb = (EPI >= 2) ? (X + bz * sX) : nullptr;

    const int m0 = blockIdx.y * BM;
    const int n0 = blockIdx.x * BN;
    const int tid = threadIdx.x;
    const int tx = tid & 15;        // n-dimension thread coord
    const int ty = tid >> 4;        // m-dimension thread coord

    float acc[TM][TN] = {};

    for (int k0 = 0; k0 < K; k0 += BKT) {
        // ---- load A tile ----
        if (AL == 1) {
            int k = tid >> 4;
            int m = (tid & 15) << 2;
            float4 v = *reinterpret_cast<const float4*>(
                A + (long long)(k0 + k) * lda + (m0 + m));
            *reinterpret_cast<float4*>(&As[k][m]) = v;
        } else {
            int m = tid >> 2;
            int kq = (tid & 3) << 2;
            float4 v = *reinterpret_cast<const float4*>(
                A + (long long)(m0 + m) * lda + (k0 + kq));
            As[kq + 0][m] = v.x; As[kq + 1][m] = v.y;
            As[kq + 2][m] = v.z; As[kq + 3][m] = v.w;
        }
        // ---- load B tile ----
        if (BL == 0) {
            int k = tid >> 4;
            int n = (tid & 15) << 2;
            float4 v = *reinterpret_cast<const float4*>(
                B + (long long)(k0 + k) * ldb + (n0 + n));
            *reinterpret_cast<float4*>(&Bs[k][n]) = v;
        } else {
            int n = tid >> 2;
            int kq = (tid & 3) << 2;
            float4 v = *reinterpret_cast<const float4*>(
                B + (long long)(n0 + n) * ldb + (k0 + kq));
            Bs[kq + 0][n] = v.x; Bs[kq + 1][n] = v.y;
            Bs[kq + 2][n] = v.z; Bs[kq + 3][n] = v.w;
        }
        __syncthreads();

#pragma unroll
        for (int k = 0; k < BKT; k++) {
            float a[TM], bb[TN];
#pragma unroll
            for (int i = 0; i < TM; i++) a[i] = As[k][ty * TM + i];
#pragma unroll
            for (int j = 0; j < TN; j++) bb[j] = Bs[k][tx * TN + j];
#pragma unroll
            for (int i = 0; i < TM; i++)
#pragma unroll
                for (int j = 0; j < TN; j++)
                    acc[i][j] = fmaf(a[i], bb[j], acc[i][j]);
        }
        __syncthreads();
    }

    // ---- epilogue + store ----
#pragma unroll
    for (int i = 0; i < TM; i++) {
        int m = m0 + ty * TM + i;
        float bi = (EPI >= 1) ? bias[m] : 0.f;
#pragma unroll
        for (int j = 0; j < TN; j++) {
            int n = n0 + tx * TN + j;
            float v = acc[i][j] + bi;
            if (EPI == 2) v *= Xb[(long long)m * ldx + n];
            if (EPI == 3) v += Xb[(long long)m * ldx + n];
            C[(long long)m * ldc + n] = v;
        }
    }
}

// ---------------------------------------------------------------------------
// Row softmax over last dim (T = 1024), in place. One block per row.
// ---------------------------------------------------------------------------
__global__ __launch_bounds__(256) void softmax_k(float* __restrict__ P)
{
    long long row = blockIdx.x;
    float* p = P + row * (long long)S_;
    int t = threadIdx.x;

    float4 v = reinterpret_cast<float4*>(p)[t];
    float mx = fmaxf(fmaxf(v.x, v.y), fmaxf(v.z, v.w));

    __shared__ float rm[8];
    __shared__ float rs[8];
#pragma unroll
    for (int o = 16; o; o >>= 1) mx = fmaxf(mx, __shfl_xor_sync(0xffffffffu, mx, o));
    if ((t & 31) == 0) rm[t >> 5] = mx;
    __syncthreads();
    mx = rm[0];
#pragma unroll
    for (int i = 1; i < 8; i++) mx = fmaxf(mx, rm[i]);

    v.x = __expf(v.x - mx);
    v.y = __expf(v.y - mx);
    v.z = __expf(v.z - mx);
    v.w = __expf(v.w - mx);

    float s = v.x + v.y + v.z + v.w;
#pragma unroll
    for (int o = 16; o; o >>= 1) s += __shfl_xor_sync(0xffffffffu, s, o);
    if ((t & 31) == 0) rs[t >> 5] = s;
    __syncthreads();
    s = 0.f;
#pragma unroll
    for (int i = 0; i < 8; i++) s += rs[i];

    float inv = 1.f / s;
    v.x *= inv; v.y *= inv; v.z *= inv; v.w *= inv;
    reinterpret_cast<float4*>(p)[t] = v;
}

// ---------------------------------------------------------------------------
// Router mean pool: g[b, j] = mean_s( j<C ? lidar[b,j,s] : hsi[b,j-C,s] )
// One warp per (b, j) row. grid = B*2C/8, block = 256.
// ---------------------------------------------------------------------------
__global__ __launch_bounds__(256) void pool_k(const float* __restrict__ lidar,
                                              const float* __restrict__ hsi,
                                              float* __restrict__ g)
{
    int row = blockIdx.x * 8 + (threadIdx.x >> 5);
    int lane = threadIdx.x & 31;
    int b = row >> 9;
    int ch = row & 511;
    const float* src = (ch < C_)
        ? lidar + ((long long)b * C_ + ch) * S_
        : hsi + ((long long)b * C_ + (ch - C_)) * S_;
    float s = 0.f;
#pragma unroll 8
    for (int i = lane; i < S_; i += 32) s += src[i];
#pragma unroll
    for (int o = 16; o; o >>= 1) s += __shfl_xor_sync(0xffffffffu, s, o);
    if (lane == 0) g[row] = s * (1.f / (float)S_);
}

// ---------------------------------------------------------------------------
// Router MLP: sigmoid(relu(g @ W1^T + b1) @ W2^T + b2). grid = B, block = HID.
// ---------------------------------------------------------------------------
__global__ __launch_bounds__(128) void router_k(const float* __restrict__ g,
    const float* __restrict__ w1, const float* __restrict__ b1,
    const float* __restrict__ w2, const float* __restrict__ b2,
    float* __restrict__ out)
{
    int b = blockIdx.x;
    int t = threadIdx.x;
    __shared__ float hs[HID_];

    const float* gb = g + b * (2 * C_);
    const float* wr = w1 + t * (2 * C_);
    float s0 = 0.f, s1 = 0.f, s2 = 0.f, s3 = 0.f;
    for (int c = 0; c < 2 * C_; c += 4) {
        s0 = fmaf(gb[c + 0], wr[c + 0], s0);
        s1 = fmaf(gb[c + 1], wr[c + 1], s1);
        s2 = fmaf(gb[c + 2], wr[c + 2], s2);
        s3 = fmaf(gb[c + 3], wr[c + 3], s3);
    }
    hs[t] = fmaxf(s0 + s1 + s2 + s3 + b1[t], 0.f);
    __syncthreads();

    if (t < NPATH_) {
        const float* wr2 = w2 + t * HID_;
        float s = b2[t];
        for (int c = 0; c < HID_; c++) s = fmaf(hs[c], wr2[c], s);
        out[b * NPATH_ + t] = 1.f / (1.f + expf(-s));
    }
}

// ---------------------------------------------------------------------------
// kernel_launch: 13 launches, fully graph-capturable, allocation-free.
// ---------------------------------------------------------------------------
extern "C" void kernel_launch(void* const* d_in, const int* in_sizes, int n_in,
                              void* d_out, int out_size)
{
    const float* lidar  = (const float*)d_in[0];
    const float* hsi    = (const float*)d_in[1];
    const float* x      = (const float*)d_in[2];
    const float* Wq     = (const float*)d_in[3];
    const float* bq     = (const float*)d_in[4];
    const float* Wk     = (const float*)d_in[5];
    const float* bk     = (const float*)d_in[6];
    const float* Wv     = (const float*)d_in[7];
    const float* bv     = (const float*)d_in[8];
    const float* conv_w = (const float*)d_in[9];
    const float* conv_b = (const float*)d_in[10];
    const float* r_w1   = (const float*)d_in[11];
    const float* r_b1   = (const float*)d_in[12];
    const float* r_w2   = (const float*)d_in[13];
    const float* r_b2   = (const float*)d_in[14];

    float* emb  = (float*)d_out;                          // [B, C, H, W]
    float* prob = emb + (long long)B_ * C_ * S_;          // [B, NPATH]

    float *Ql, *Kl, *Qh, *Kh, *QV1, *QV2, *P, *cat, *pool;
    cudaGetSymbolAddress((void**)&Ql,  g_Ql);
    cudaGetSymbolAddress((void**)&Kl,  g_Kl);
    cudaGetSymbolAddress((void**)&Qh,  g_Qh);
    cudaGetSymbolAddress((void**)&Kh,  g_Kh);
    cudaGetSymbolAddress((void**)&QV1, g_QV1);
    cudaGetSymbolAddress((void**)&QV2, g_QV2);
    cudaGetSymbolAddress((void**)&P,   g_P);
    cudaGetSymbolAddress((void**)&cat, g_cat);
    cudaGetSymbolAddress((void**)&pool, g_pool);

    const long long CS = (long long)C_ * S_;   // 262144 per-batch [c][s] plane
    const long long SS = (long long)S_ * S_;   // 1048576 per-batch [s][t] plane

    dim3 blk(256);

    // Router path
    pool_k<<<B_ * 2 * C_ / 8, 256>>>(lidar, hsi, pool);
    router_k<<<B_, 128>>>(pool, r_w1, r_b1, r_w2, r_b2, prob);

    // Projections: OUT[b][o][s] = sum_c W[o][c] * IN[b][c][s] + bias[o]
    dim3 gProj(S_ / BN, C_ / BM, B_);
    gemm_k<0, 0, 1><<<gProj, blk>>>(Wq, lidar, Ql, bq, nullptr,
                                    C_, C_, S_, S_, 0, 0, CS, CS, 0);
    gemm_k<0, 0, 1><<<gProj, blk>>>(Wk, lidar, Kl, bk, nullptr,
                                    C_, C_, S_, S_, 0, 0, CS, CS, 0);
    gemm_k<0, 0, 1><<<gProj, blk>>>(Wq, hsi, Qh, bq, nullptr,
                                    C_, C_, S_, S_, 0, 0, CS, CS, 0);
    gemm_k<0, 0, 1><<<gProj, blk>>>(Wk, hsi, Kh, bk, nullptr,
                                    C_, C_, S_, S_, 0, 0, CS, CS, 0);
    // Bilinear values: QV1 = Ql * (Wv@hsi + bv), QV2 = Qh * (Wv@lidar + bv)
    gemm_k<0, 0, 2><<<gProj, blk>>>(Wv, hsi, QV1, bv, Ql,
                                    C_, C_, S_, S_, S_, 0, CS, CS, CS);
    gemm_k<0, 0, 2><<<gProj, blk>>>(Wv, lidar, QV2, bv, Qh,
                                    C_, C_, S_, S_, S_, 0, CS, CS, CS);

    // Logits: P[dir][b][s][t] = sum_c Q[b][c][s] * K[b][c][t]
    dim3 gLog(S_ / BN, S_ / BM, B_);
    gemm_k<1, 0, 0><<<gLog, blk>>>(Ql, Kl, P, nullptr, nullptr,
                                   C_, S_, S_, S_, 0, CS, CS, SS, 0);
    gemm_k<1, 0, 0><<<gLog, blk>>>(Qh, Kh, P + (long long)B_ * SS, nullptr, nullptr,
                                   C_, S_, S_, S_, 0, CS, CS, SS, 0);

    // Softmax over t, both directions in one launch
    softmax_k<<<2 * B_ * S_, 256>>>(P);

    // PV: out[b][c][s] = sum_t QV[b][c][t] * P[b][s][t]
    // h_emb (dir0, q from lidar) -> cat channels [C, 2C); l_emb (dir1) -> [0, C)
    dim3 gPV(S_ / BN, C_ / BM, B_);
    gemm_k<0, 1, 0><<<gPV, blk>>>(QV1, P, cat + CS, nullptr, nullptr,
                                  S_, S_, S_, S_, 0, CS, SS, 2 * CS, 0);
    gemm_k<0, 1, 0><<<gPV, blk>>>(QV2, P + (long long)B_ * SS, cat, nullptr, nullptr,
                                  S_, S_, S_, S_, 0, CS, SS, 2 * CS, 0);

    // 1x1 conv + residual: emb[b][o][s] = sum_i conv_w[o][i]*cat[b][i][s] + conv_b[o] + x[b][o][s]
    gemm_k<0, 0, 3><<<gProj, blk>>>(conv_w, cat, emb, conv_b, x,
                                    2 * C_, 2 * C_, S_, S_, S_, 0, 2 * CS, CS, CS);
}

// round 10
// speedup vs baseline: 1.1337x; 1.1337x over previous
#include <cuda_runtime.h>
#include <cuda_bf16.h>
#include <math.h>
#include <stdint.h>

// Problem constants
#define B_ 32
#define C_ 256
#define S_ 1024
#define HID_ 128
#define NPATH_ 4

// ---------------------------------------------------------------------------
// Static device scratch
// ---------------------------------------------------------------------------
__device__ float g_Ql[B_ * C_ * S_];
__device__ float g_Kl[B_ * C_ * S_];
__device__ float g_Qh[B_ * C_ * S_];
__device__ float g_Kh[B_ * C_ * S_];
__device__ float g_QV1[B_ * C_ * S_];
__device__ float g_QV2[B_ * C_ * S_];
__device__ float g_P[2LL * B_ * S_ * S_];
__device__ float g_cat[B_ * 2 * C_ * S_];
__device__ float g_pool[B_ * 2 * C_];

// ---------------------------------------------------------------------------
// bf16 hi/lo split of an fp32 value: v ~= hi + lo, each bf16.
// ---------------------------------------------------------------------------
__device__ __forceinline__ void cvt_hilo(float v, uint16_t& h, uint16_t& l) {
    __nv_bfloat16 bh = __float2bfloat16_rn(v);
    float hf = __bfloat162float(bh);
    __nv_bfloat16 bl = __float2bfloat16_rn(v - hf);
    h = __bfloat16_as_ushort(bh);
    l = __bfloat16_as_ushort(bl);
}

// mma.sync m16n8k16 row.col f32.bf16.bf16.f32 (sm_80+ PTX; HMMA on sm_103)
__device__ __forceinline__ void mma16816(float* c, const uint32_t* a, const uint32_t* b) {
    asm volatile(
        "mma.sync.aligned.m16n8k16.row.col.f32.bf16.bf16.f32 "
        "{%0,%1,%2,%3}, {%4,%5,%6,%7}, {%8,%9}, {%0,%1,%2,%3};"
        : "+f"(c[0]), "+f"(c[1]), "+f"(c[2]), "+f"(c[3])
        : "r"(a[0]), "r"(a[1]), "r"(a[2]), "r"(a[3]),
          "r"(b[0]), "r"(b[1]));
}

// ---------------------------------------------------------------------------
// Tensor-core GEMM (HMMA), fp32-in/out via bf16 hi+lo split (3 MMA passes).
// C[m,n] = sum_k opA(m,k)*opB(k,n)  (+ epilogue), tile 128x64, K-chunk 32.
//   AL=0: A [m][k] (k contig) / AL=1: A [k][m] (m contig)
//   BL=0: B [k][n] (n contig) / BL=1: B [n][k] (k contig)
//   EPI=0 none, 1 +bias[m], 2 (acc+bias)*X[m,n], 3 acc+bias+X[m,n]
// grid = (N/64, M/128, batch), block = 256 (8 warps: 4 along M x 2 along N)
// ---------------------------------------------------------------------------
constexpr int TBM = 128, TBN = 64, TBK = 32;
constexpr int PITCH = 40;   // bf16 per smem row (80 B) -> conflict-free frags

template<int AL, int BL, int EPI>
__global__ __launch_bounds__(256) void tgemm(
    const float* __restrict__ A, const float* __restrict__ B,
    float* __restrict__ Cc, const float* __restrict__ bias,
    const float* __restrict__ X,
    int K, int lda, int ldb, int ldc, int ldx,
    long long sA, long long sB, long long sC, long long sX)
{
    __shared__ __align__(16) uint16_t As_h[TBM][PITCH];
    __shared__ __align__(16) uint16_t As_l[TBM][PITCH];
    __shared__ __align__(16) uint16_t Bs_h[TBN][PITCH];
    __shared__ __align__(16) uint16_t Bs_l[TBN][PITCH];

    const int tid = threadIdx.x;
    const int wid = tid >> 5;
    const int lane = tid & 31;
    const int grp = lane >> 2;      // 0..7
    const int tig = lane & 3;       // 0..3
    const int warp_m = wid & 3;     // 0..3 (M)
    const int warp_n = wid >> 2;    // 0..1 (N)

    long long bz = blockIdx.z;
    const float* Ab = A + bz * sA;
    const float* Bb = B + bz * sB;
    float* Cb = Cc + bz * sC;
    const float* Xb = (EPI >= 2) ? (X + bz * sX) : nullptr;
    const int m0 = blockIdx.y * TBM;
    const int n0 = blockIdx.x * TBN;

    float acc[2][4][4];
#pragma unroll
    for (int mt = 0; mt < 2; mt++)
#pragma unroll
        for (int nt = 0; nt < 4; nt++)
#pragma unroll
            for (int r = 0; r < 4; r++) acc[mt][nt][r] = 0.f;

    for (int k0 = 0; k0 < K; k0 += TBK) {
        // ---- stage A (128 x 32) as hi/lo bf16 ----
        if (AL == 0) {
#pragma unroll
            for (int i = 0; i < 4; i++) {
                int lin = tid + 256 * i;
                int m = lin >> 3;
                int kq = (lin & 7) << 2;
                float4 v = *reinterpret_cast<const float4*>(
                    Ab + (long long)(m0 + m) * lda + (k0 + kq));
                uint16_t h0, l0, h1, l1, h2, l2, h3, l3;
                cvt_hilo(v.x, h0, l0); cvt_hilo(v.y, h1, l1);
                cvt_hilo(v.z, h2, l2); cvt_hilo(v.w, h3, l3);
                *(uint32_t*)&As_h[m][kq]     = (uint32_t)h0 | ((uint32_t)h1 << 16);
                *(uint32_t*)&As_h[m][kq + 2] = (uint32_t)h2 | ((uint32_t)h3 << 16);
                *(uint32_t*)&As_l[m][kq]     = (uint32_t)l0 | ((uint32_t)l1 << 16);
                *(uint32_t*)&As_l[m][kq + 2] = (uint32_t)l2 | ((uint32_t)l3 << 16);
            }
        } else {
#pragma unroll
            for (int i = 0; i < 4; i++) {
                int lin = tid + 256 * i;
                int k = lin >> 5;
                int m4 = (lin & 31) << 2;
                float4 v = *reinterpret_cast<const float4*>(
                    Ab + (long long)(k0 + k) * lda + (m0 + m4));
                uint16_t h, l;
                float vv[4] = {v.x, v.y, v.z, v.w};
#pragma unroll
                for (int j = 0; j < 4; j++) {
                    cvt_hilo(vv[j], h, l);
                    As_h[m4 + j][k] = h;
                    As_l[m4 + j][k] = l;
                }
            }
        }
        // ---- stage B (64 x 32) as hi/lo bf16, rows = n ----
        if (BL == 0) {
#pragma unroll
            for (int i = 0; i < 2; i++) {
                int lin = tid + 256 * i;
                int k = lin >> 4;
                int n4 = (lin & 15) << 2;
                float4 v = *reinterpret_cast<const float4*>(
                    Bb + (long long)(k0 + k) * ldb + (n0 + n4));
                uint16_t h, l;
                float vv[4] = {v.x, v.y, v.z, v.w};
#pragma unroll
                for (int j = 0; j < 4; j++) {
                    cvt_hilo(vv[j], h, l);
                    Bs_h[n4 + j][k] = h;
                    Bs_l[n4 + j][k] = l;
                }
            }
        } else {
#pragma unroll
            for (int i = 0; i < 2; i++) {
                int lin = tid + 256 * i;
                int n = lin >> 3;
                int kq = (lin & 7) << 2;
                float4 v = *reinterpret_cast<const float4*>(
                    Bb + (long long)(n0 + n) * ldb + (k0 + kq));
                uint16_t h0, l0, h1, l1, h2, l2, h3, l3;
                cvt_hilo(v.x, h0, l0); cvt_hilo(v.y, h1, l1);
                cvt_hilo(v.z, h2, l2); cvt_hilo(v.w, h3, l3);
                *(uint32_t*)&Bs_h[n][kq]     = (uint32_t)h0 | ((uint32_t)h1 << 16);
                *(uint32_t*)&Bs_h[n][kq + 2] = (uint32_t)h2 | ((uint32_t)h3 << 16);
                *(uint32_t*)&Bs_l[n][kq]     = (uint32_t)l0 | ((uint32_t)l1 << 16);
                *(uint32_t*)&Bs_l[n][kq + 2] = (uint32_t)l2 | ((uint32_t)l3 << 16);
            }
        }
        __syncthreads();

        // ---- two k16 steps of HMMA ----
#pragma unroll
        for (int ks = 0; ks < 2; ks++) {
            const int kb = ks * 16;
            uint32_t ah[2][4], al_[2][4], bh[4][2], bl_[4][2];
#pragma unroll
            for (int mt = 0; mt < 2; mt++) {
                int r0 = warp_m * 32 + mt * 16 + grp;
                int c0 = kb + tig * 2;
                ah[mt][0] = *(const uint32_t*)&As_h[r0][c0];
                ah[mt][1] = *(const uint32_t*)&As_h[r0 + 8][c0];
                ah[mt][2] = *(const uint32_t*)&As_h[r0][c0 + 8];
                ah[mt][3] = *(const uint32_t*)&As_h[r0 + 8][c0 + 8];
                al_[mt][0] = *(const uint32_t*)&As_l[r0][c0];
                al_[mt][1] = *(const uint32_t*)&As_l[r0 + 8][c0];
                al_[mt][2] = *(const uint32_t*)&As_l[r0][c0 + 8];
                al_[mt][3] = *(const uint32_t*)&As_l[r0 + 8][c0 + 8];
            }
#pragma unroll
            for (int nt = 0; nt < 4; nt++) {
                int nr = warp_n * 32 + nt * 8 + grp;
                int c0 = kb + tig * 2;
                bh[nt][0] = *(const uint32_t*)&Bs_h[nr][c0];
                bh[nt][1] = *(const uint32_t*)&Bs_h[nr][c0 + 8];
                bl_[nt][0] = *(const uint32_t*)&Bs_l[nr][c0];
                bl_[nt][1] = *(const uint32_t*)&Bs_l[nr][c0 + 8];
            }
#pragma unroll
            for (int mt = 0; mt < 2; mt++)
#pragma unroll
                for (int nt = 0; nt < 4; nt++) {
                    mma16816(acc[mt][nt], ah[mt], bh[nt]);
                    mma16816(acc[mt][nt], ah[mt], bl_[nt]);
                    mma16816(acc[mt][nt], al_[mt], bh[nt]);
                }
        }
        __syncthreads();
    }

    // ---- epilogue ----
    const int mbase = m0 + warp_m * 32;
    const int nbase = n0 + warp_n * 32;
#pragma unroll
    for (int mt = 0; mt < 2; mt++) {
        int mrow = mbase + mt * 16 + grp;
        float bi0 = 0.f, bi1 = 0.f;
        if (EPI >= 1) { bi0 = bias[mrow]; bi1 = bias[mrow + 8]; }
#pragma unroll
        for (int nt = 0; nt < 4; nt++) {
            int n = nbase + nt * 8 + tig * 2;
            float2 v0, v1;
            v0.x = acc[mt][nt][0] + bi0;
            v0.y = acc[mt][nt][1] + bi0;
            v1.x = acc[mt][nt][2] + bi1;
            v1.y = acc[mt][nt][3] + bi1;
            if (EPI == 2) {
                float2 x0 = *reinterpret_cast<const float2*>(Xb + (long long)mrow * ldx + n);
                float2 x1 = *reinterpret_cast<const float2*>(Xb + (long long)(mrow + 8) * ldx + n);
                v0.x *= x0.x; v0.y *= x0.y;
                v1.x *= x1.x; v1.y *= x1.y;
            }
            if (EPI == 3) {
                float2 x0 = *reinterpret_cast<const float2*>(Xb + (long long)mrow * ldx + n);
                float2 x1 = *reinterpret_cast<const float2*>(Xb + (long long)(mrow + 8) * ldx + n);
                v0.x += x0.x; v0.y += x0.y;
                v1.x += x1.x; v1.y += x1.y;
            }
            *reinterpret_cast<float2*>(Cb + (long long)mrow * ldc + n) = v0;
            *reinterpret_cast<float2*>(Cb + (long long)(mrow + 8) * ldc + n) = v1;
        }
    }
}

// ---------------------------------------------------------------------------
// Row softmax over last dim (1024), in place. One block per row.
// ---------------------------------------------------------------------------
__global__ __launch_bounds__(256) void softmax_k(float* __restrict__ P)
{
    long long row = blockIdx.x;
    float* p = P + row * (long long)S_;
    int t = threadIdx.x;

    float4 v = reinterpret_cast<float4*>(p)[t];
    float mx = fmaxf(fmaxf(v.x, v.y), fmaxf(v.z, v.w));

    __shared__ float rm[8];
    __shared__ float rs[8];
#pragma unroll
    for (int o = 16; o; o >>= 1) mx = fmaxf(mx, __shfl_xor_sync(0xffffffffu, mx, o));
    if ((t & 31) == 0) rm[t >> 5] = mx;
    __syncthreads();
    mx = rm[0];
#pragma unroll
    for (int i = 1; i < 8; i++) mx = fmaxf(mx, rm[i]);

    v.x = __expf(v.x - mx);
    v.y = __expf(v.y - mx);
    v.z = __expf(v.z - mx);
    v.w = __expf(v.w - mx);

    float s = v.x + v.y + v.z + v.w;
#pragma unroll
    for (int o = 16; o; o >>= 1) s += __shfl_xor_sync(0xffffffffu, s, o);
    if ((t & 31) == 0) rs[t >> 5] = s;
    __syncthreads();
    s = 0.f;
#pragma unroll
    for (int i = 0; i < 8; i++) s += rs[i];

    float inv = 1.f / s;
    v.x *= inv; v.y *= inv; v.z *= inv; v.w *= inv;
    reinterpret_cast<float4*>(p)[t] = v;
}

// ---------------------------------------------------------------------------
// Router mean pool + MLP
// ---------------------------------------------------------------------------
__global__ __launch_bounds__(256) void pool_k(const float* __restrict__ lidar,
                                              const float* __restrict__ hsi,
                                              float* __restrict__ g)
{
    int row = blockIdx.x * 8 + (threadIdx.x >> 5);
    int lane = threadIdx.x & 31;
    int b = row >> 9;
    int ch = row & 511;
    const float* src = (ch < C_)
        ? lidar + ((long long)b * C_ + ch) * S_
        : hsi + ((long long)b * C_ + (ch - C_)) * S_;
    float s = 0.f;
#pragma unroll 8
    for (int i = lane; i < S_; i += 32) s += src[i];
#pragma unroll
    for (int o = 16; o; o >>= 1) s += __shfl_xor_sync(0xffffffffu, s, o);
    if (lane == 0) g[row] = s * (1.f / (float)S_);
}

__global__ __launch_bounds__(128) void router_k(const float* __restrict__ g,
    const float* __restrict__ w1, const float* __restrict__ b1,
    const float* __restrict__ w2, const float* __restrict__ b2,
    float* __restrict__ out)
{
    int b = blockIdx.x;
    int t = threadIdx.x;
    __shared__ float hs[HID_];

    const float* gb = g + b * (2 * C_);
    const float* wr = w1 + t * (2 * C_);
    float s0 = 0.f, s1 = 0.f, s2 = 0.f, s3 = 0.f;
    for (int c = 0; c < 2 * C_; c += 4) {
        s0 = fmaf(gb[c + 0], wr[c + 0], s0);
        s1 = fmaf(gb[c + 1], wr[c + 1], s1);
        s2 = fmaf(gb[c + 2], wr[c + 2], s2);
        s3 = fmaf(gb[c + 3], wr[c + 3], s3);
    }
    hs[t] = fmaxf(s0 + s1 + s2 + s3 + b1[t], 0.f);
    __syncthreads();

    if (t < NPATH_) {
        const float* wr2 = w2 + t * HID_;
        float s = b2[t];
        for (int c = 0; c < HID_; c++) s = fmaf(hs[c], wr2[c], s);
        out[b * NPATH_ + t] = 1.f / (1.f + expf(-s));
    }
}

// ---------------------------------------------------------------------------
// kernel_launch: graph-capturable, allocation-free.
// ---------------------------------------------------------------------------
extern "C" void kernel_launch(void* const* d_in, const int* in_sizes, int n_in,
                              void* d_out, int out_size)
{
    const float* lidar  = (const float*)d_in[0];
    const float* hsi    = (const float*)d_in[1];
    const float* x      = (const float*)d_in[2];
    const float* Wq     = (const float*)d_in[3];
    const float* bq     = (const float*)d_in[4];
    const float* Wk     = (const float*)d_in[5];
    const float* bk     = (const float*)d_in[6];
    const float* Wv     = (const float*)d_in[7];
    const float* bv     = (const float*)d_in[8];
    const float* conv_w = (const float*)d_in[9];
    const float* conv_b = (const float*)d_in[10];
    const float* r_w1   = (const float*)d_in[11];
    const float* r_b1   = (const float*)d_in[12];
    const float* r_w2   = (const float*)d_in[13];
    const float* r_b2   = (const float*)d_in[14];

    float* emb  = (float*)d_out;
    float* prob = emb + (long long)B_ * C_ * S_;

    float *Ql, *Kl, *Qh, *Kh, *QV1, *QV2, *P, *cat, *pool;
    cudaGetSymbolAddress((void**)&Ql,  g_Ql);
    cudaGetSymbolAddress((void**)&Kl,  g_Kl);
    cudaGetSymbolAddress((void**)&Qh,  g_Qh);
    cudaGetSymbolAddress((void**)&Kh,  g_Kh);
    cudaGetSymbolAddress((void**)&QV1, g_QV1);
    cudaGetSymbolAddress((void**)&QV2, g_QV2);
    cudaGetSymbolAddress((void**)&P,   g_P);
    cudaGetSymbolAddress((void**)&cat, g_cat);
    cudaGetSymbolAddress((void**)&pool, g_pool);

    const long long CS = (long long)C_ * S_;   // per-batch [c][s] plane
    const long long SS = (long long)S_ * S_;   // per-batch [s][t] plane

    // Router path
    pool_k<<<B_ * 2 * C_ / 8, 256>>>(lidar, hsi, pool);
    router_k<<<B_, 128>>>(pool, r_w1, r_b1, r_w2, r_b2, prob);

    dim3 blk(256);
    dim3 gProj(S_ / TBN, C_ / TBM, B_);   // (16, 2, 32)
    dim3 gLog(S_ / TBN, S_ / TBM, B_);    // (16, 8, 32)

    // Projections: OUT[b][o][s] = W[o][c] * IN[b][c][s] + bias[o]
    tgemm<0,0,1><<<gProj, blk>>>(Wq, lidar, Ql, bq, nullptr,
                                 C_, C_, S_, S_, 0, 0, CS, CS, 0);
    tgemm<0,0,1><<<gProj, blk>>>(Wk, lidar, Kl, bk, nullptr,
                                 C_, C_, S_, S_, 0, 0, CS, CS, 0);
    tgemm<0,0,1><<<gProj, blk>>>(Wq, hsi, Qh, bq, nullptr,
                                 C_, C_, S_, S_, 0, 0, CS, CS, 0);
    tgemm<0,0,1><<<gProj, blk>>>(Wk, hsi, Kh, bk, nullptr,
                                 C_, C_, S_, S_, 0, 0, CS, CS, 0);
    // Bilinear values: QV1 = (Wv@hsi + bv) * Ql ; QV2 = (Wv@lidar + bv) * Qh
    tgemm<0,0,2><<<gProj, blk>>>(Wv, hsi, QV1, bv, Ql,
                                 C_, C_, S_, S_, S_, 0, CS, CS, CS);
    tgemm<0,0,2><<<gProj, blk>>>(Wv, lidar, QV2, bv, Qh,
                                 C_, C_, S_, S_, S_, 0, CS, CS, CS);

    // Logits: P[dir][b][s][t] = sum_c Q[b][c][s] * K[b][c][t]
    tgemm<1,0,0><<<gLog, blk>>>(Ql, Kl, P, nullptr, nullptr,
                                C_, S_, S_, S_, 0, CS, CS, SS, 0);
    tgemm<1,0,0><<<gLog, blk>>>(Qh, Kh, P + (long long)B_ * SS, nullptr, nullptr,
                                C_, S_, S_, S_, 0, CS, CS, SS, 0);

    softmax_k<<<2 * B_ * S_, 256>>>(P);

    // PV: out[b][c][s] = sum_t QV[b][c][t] * P[b][s][t]
    tgemm<0,1,0><<<gProj, blk>>>(QV1, P, cat + CS, nullptr, nullptr,
                                 S_, S_, S_, S_, 0, CS, SS, 2 * CS, 0);
    tgemm<0,1,0><<<gProj, blk>>>(QV2, P + (long long)B_ * SS, cat, nullptr, nullptr,
                                 S_, S_, S_, S_, 0, CS, SS, 2 * CS, 0);

    // 1x1 conv + residual
    tgemm<0,0,3><<<gProj, blk>>>(conv_w, cat, emb, conv_b, x,
                                 2 * C_, 2 * C_, S_, S_, S_, 0, 2 * CS, CS, CS);
}